// round 12
// baseline (speedup 1.0000x reference)
#include <cuda_runtime.h>
#include <cuda_bf16.h>
#include <cstdint>

#define N_NODES 100000
#define E_EDGES 1600000
#define HDIM    128
#define BMW     ((N_NODES + 31) / 32)     // 3125 bitmap words
#define E4      (E_EDGES / 4)             // 400000 edge quads
#define GE4     ((E4 + 255) / 256)        // 1563 edge blocks
#define GN      ((N_NODES + 255) / 256)   // 391

#define CAP_V2   64
#define CAP_EV2  256
#define CAP_H2   4096
#define CAP_EB2  8192
#define CAP_H1   65536
#define CAP_EB1  131072

// ---------------- scratch (static device globals) ------------------------------
__device__ int      g_is64;
__device__ int      g_degi[N_NODES];
__device__ uint32_t g_bmV2[BMW], g_bmH2[BMW], g_bmH1[BMW];
__device__ int      g_slotV2[N_NODES], g_slotH2[N_NODES], g_slotH1[N_NODES];
__device__ int      g_LV2[CAP_V2], g_LH2[CAP_H2], g_LH1[CAP_H1];
__device__ int      g_EV2[CAP_EV2];
__device__ int2     g_EB1[CAP_EB1], g_EB2[CAP_EB2];
__device__ int      g_cntV2, g_cntEV2, g_cntH2, g_cntH1, g_cntEB1, g_cntEB2;
__device__ __align__(16) float g_h1s [(size_t)CAP_H1 * HDIM];  // h1 compact
__device__ __align__(16) float g_acc1[(size_t)CAP_H2 * HDIM];  // agg1 accum
__device__ __align__(16) float g_h2s [(size_t)CAP_H2 * HDIM];  // h2 compact
// pre-tiled bf16 weight images (exact SMEM 8x8-block layout, 32KB each)
__device__ __align__(16) __nv_bfloat16 g_w1hi[16384];
__device__ __align__(16) __nv_bfloat16 g_w1lo[16384];
__device__ __align__(16) __nv_bfloat16 g_w2hi[16384];
__device__ __align__(16) __nv_bfloat16 g_w2lo[16384];

// ---------------- PTX helpers ----------------------------------------------------
__device__ __forceinline__ uint32_t smem_u32(const void* p) {
    uint32_t a;
    asm("{ .reg .u64 t; cvta.to.shared.u64 t, %1; cvt.u32.u64 %0, t; }" : "=r"(a) : "l"(p));
    return a;
}
__device__ __forceinline__ void ldsm4(uint32_t* r, uint32_t addr) {
    asm volatile("ldmatrix.sync.aligned.m8n8.x4.shared.b16 {%0,%1,%2,%3}, [%4];"
                 : "=r"(r[0]), "=r"(r[1]), "=r"(r[2]), "=r"(r[3]) : "r"(addr));
}
__device__ __forceinline__ void mma_bf16(float* c, const uint32_t* a, uint32_t b0, uint32_t b1) {
    asm volatile("mma.sync.aligned.m16n8k16.row.col.f32.bf16.bf16.f32 "
                 "{%0,%1,%2,%3}, {%4,%5,%6,%7}, {%8,%9}, {%0,%1,%2,%3};"
                 : "+f"(c[0]), "+f"(c[1]), "+f"(c[2]), "+f"(c[3])
                 : "r"(a[0]), "r"(a[1]), "r"(a[2]), "r"(a[3]), "r"(b0), "r"(b1));
}
__device__ __forceinline__ uint32_t tile_addr(int r, int k) {
    uint32_t blk = (uint32_t)(((r >> 3) * 8 + (k >> 4)) * 2 + ((k >> 3) & 1));
    return blk * 128 + (uint32_t)((r & 7) * 16 + (k & 7) * 2);
}
__device__ __forceinline__ float node_dinv(int v) {
    return rsqrtf((float)g_degi[v] + 1.f);
}
__device__ __forceinline__ void load_dst4(const void* eiv, int i, int* d) {
    if (g_is64) {
        const longlong2* p = (const longlong2*)((const long long*)eiv + E_EDGES);
        longlong2 a = p[i * 2];
        longlong2 b = p[i * 2 + 1];
        d[0] = (int)a.x; d[1] = (int)a.y; d[2] = (int)b.x; d[3] = (int)b.y;
    } else {
        int4 v = ((const int4*)((const int*)eiv + E_EDGES))[i];
        d[0] = v.x; d[1] = v.y; d[2] = v.z; d[3] = v.w;
    }
#pragma unroll
    for (int j = 0; j < 4; j++)
        if ((unsigned)d[j] >= N_NODES) d[j] = 0;
}
__device__ __forceinline__ int load_src(const void* eiv, int e) {
    int s = g_is64 ? (int)((const long long*)eiv)[e] : ((const int*)eiv)[e];
    if ((unsigned)s >= N_NODES) s = 0;
    return s;
}
__device__ __forceinline__ void try_append(uint32_t* bm, int* slotArr, int* list,
                                           int* cnt, int cap, int node) {
    uint32_t mask = 1u << (node & 31);
    uint32_t old = atomicOr(&bm[node >> 5], mask);
    if (!(old & mask)) {
        int s = atomicAdd(cnt, 1);
        if (s < cap) { slotArr[node] = s; list[s] = node; }
    }
}

// ---------------- init: zero degi/bitmaps/acc1 + seed node 0 ---------------------
__global__ __launch_bounds__(256) void k_init(const long long* __restrict__ ei) {
    if ((int)blockIdx.x >= GN) {
        int i = ((int)blockIdx.x - GN) * 256 + threadIdx.x;      // acc1 zero
        if (i < CAP_H2 * HDIM / 4)
            ((float4*)g_acc1)[i] = make_float4(0.f, 0.f, 0.f, 0.f);
        return;
    }
    int i = blockIdx.x * blockDim.x + threadIdx.x;
    if (i < N_NODES) g_degi[i] = 0;
    if (i >= 1 && i < BMW) { g_bmV2[i] = 0; g_bmH2[i] = 0; g_bmH1[i] = 0; }
    if (i == 0) {
        g_bmV2[0] = 1u; g_bmH2[0] = 1u; g_bmH1[0] = 1u;          // node 0 seeded
        g_slotV2[0] = 0; g_slotH2[0] = 0; g_slotH1[0] = 0;
        g_LV2[0] = 0;    g_LH2[0] = 0;   g_LH1[0] = 0;
        g_cntV2 = 1; g_cntH2 = 1; g_cntH1 = 1;
        g_cntEV2 = 0; g_cntEB1 = 0; g_cntEB2 = 0;
        int is64 = 1;
#pragma unroll
        for (int j = 0; j < 16; j++) {
            long long v = ei[j];
            if (v < 0 || v >= N_NODES) { is64 = 0; break; }
        }
        g_is64 = is64;
    }
}

// ---------------- pass 0: V2 frontier only (+ wconv on extra blocks) -------------
__global__ __launch_bounds__(256) void k_prep(const void* __restrict__ eiv,
                                              const float* __restrict__ w1,
                                              const float* __restrict__ w2) {
    if ((int)blockIdx.x >= GE4) {
        int i = ((int)blockIdx.x - GE4) * 256 + threadIdx.x;     // 0..32767
        if (i < 32768) {
            const float* w = (i < 16384) ? w1 : w2;
            __nv_bfloat16* hi = (i < 16384) ? g_w1hi : g_w2hi;
            __nv_bfloat16* lo = (i < 16384) ? g_w1lo : g_w2lo;
            int j = i & 16383;
            int k = j >> 7, n = j & 127;                          // B[n][k] = w[k][n]
            float v = w[j];
            __nv_bfloat16 h = __float2bfloat16(v);
            __nv_bfloat16 l = __float2bfloat16(v - __bfloat162float(h));
            uint32_t a = tile_addr(n, k);
            *(__nv_bfloat16*)((char*)hi + a) = h;
            *(__nv_bfloat16*)((char*)lo + a) = l;
        }
        return;
    }
    int i = blockIdx.x * 256 + threadIdx.x;
    if (i >= E4) return;
    int d[4];
    load_dst4(eiv, i, d);
#pragma unroll
    for (int j = 0; j < 4; j++) {
        if (d[j] == 0) {
            int s = load_src(eiv, i * 4 + j);
            int ev = atomicAdd(&g_cntEV2, 1);
            if (ev < CAP_EV2) g_EV2[ev] = s;
            try_append(g_bmV2, g_slotV2, g_LV2, &g_cntV2, CAP_V2, s);
            try_append(g_bmH2, g_slotH2, g_LH2, &g_cntH2, CAP_H2, s);
            try_append(g_bmH1, g_slotH1, g_LH1, &g_cntH1, CAP_H1, s);
        }
    }
}

// ---------------- pass 1: edges into V2 -> EB2, discover H2 (smem bitmap) --------
__global__ __launch_bounds__(256) void k_f1(const void* __restrict__ eiv) {
    __shared__ uint32_t sbm[BMW];
    for (int i = threadIdx.x; i < BMW; i += 256) sbm[i] = g_bmV2[i];
    __syncthreads();
    int i = blockIdx.x * 256 + threadIdx.x;
    if (i >= E4) return;
    int d[4];
    load_dst4(eiv, i, d);
#pragma unroll
    for (int j = 0; j < 4; j++) {
        int dd = d[j];
        if (sbm[dd >> 5] & (1u << (dd & 31))) {
            int s = load_src(eiv, i * 4 + j);
            int k = atomicAdd(&g_cntEB2, 1);
            if (k < CAP_EB2) g_EB2[k] = make_int2(g_slotV2[dd], s);
            try_append(g_bmH2, g_slotH2, g_LH2, &g_cntH2, CAP_H2, s);
            try_append(g_bmH1, g_slotH1, g_LH1, &g_cntH1, CAP_H1, s);
        }
    }
}

// ---------------- pass 2: edges into H2 -> EB1, discover H1 (smem bitmap) --------
__global__ __launch_bounds__(256) void k_f2(const void* __restrict__ eiv) {
    __shared__ uint32_t sbm[BMW];
    for (int i = threadIdx.x; i < BMW; i += 256) sbm[i] = g_bmH2[i];
    __syncthreads();
    int i = blockIdx.x * 256 + threadIdx.x;
    if (i >= E4) return;
    int d[4];
    load_dst4(eiv, i, d);
#pragma unroll
    for (int j = 0; j < 4; j++) {
        int dd = d[j];
        if (sbm[dd >> 5] & (1u << (dd & 31))) {
            int s = load_src(eiv, i * 4 + j);
            int k = atomicAdd(&g_cntEB1, 1);
            if (k < CAP_EB1) g_EB1[k] = make_int2(g_slotH2[dd], s);
            try_append(g_bmH1, g_slotH1, g_LH1, &g_cntH1, CAP_H1, s);
        }
    }
}

// ---------------- pass 3: restricted degree histogram (dst in H1 only) -----------
__global__ __launch_bounds__(256) void k_hist(const void* __restrict__ eiv) {
    __shared__ uint32_t sbm[BMW];
    for (int i = threadIdx.x; i < BMW; i += 256) sbm[i] = g_bmH1[i];
    __syncthreads();
    int i = blockIdx.x * 256 + threadIdx.x;
    if (i >= E4) return;
    int d[4];
    load_dst4(eiv, i, d);
#pragma unroll
    for (int j = 0; j < 4; j++) {
        int dd = d[j];
        if (sbm[dd >> 5] & (1u << (dd & 31)))
            atomicAdd(&g_degi[dd], 1);
    }
}

// ---------------- sparse HMMA GEMM --------------------------------------------
// MODE 0: rows gathered from A via idx (layer 1, A = x)
// MODE 1: rows = relu((acc1[r] + h1s[slotH1[LH2[r]]]*di)*di + bias)  (layer 2)
#define SM_AHI  0
#define SM_ALO  32768
#define SM_BHI  65536
#define SM_BLO  98304
#define SM_TOT  131072

template <int MODE>
__global__ __launch_bounds__(256)
void k_gemm_s(const float* __restrict__ A,
              const int* __restrict__ idx,
              const int* __restrict__ cntp, int cap,
              const float* __restrict__ bias,
              const __nv_bfloat16* __restrict__ Whi,
              const __nv_bfloat16* __restrict__ Wlo,
              float* __restrict__ O) {
    int cnt = *cntp; if (cnt > cap) cnt = cap;
    const int rowBase = blockIdx.x * 128;
    if (rowBase >= cnt) return;

    extern __shared__ char smem[];
    const uint32_t sbase = smem_u32(smem);
    const int tid  = threadIdx.x;
    const int wid  = tid >> 5;
    const int lane = tid & 31;

#pragma unroll
    for (int i = 0; i < 8; i++) {
        int k = i * 256 + tid;
        ((uint4*)(smem + SM_BHI))[k] = ((const uint4*)Whi)[k];
        ((uint4*)(smem + SM_BLO))[k] = ((const uint4*)Wlo)[k];
    }

#pragma unroll
    for (int i = 0; i < 16; i++) {
        int f4  = i * 256 + tid;
        int row = f4 >> 5;
        int c4  = f4 & 31;
        int r   = rowBase + row;
        float4 v = make_float4(0.f, 0.f, 0.f, 0.f);
        if (r < cnt) {
            if (MODE == 0) {
                int node = idx[r];
                v = *(const float4*)(A + (size_t)node * HDIM + c4 * 4);
            } else {
                int   node = g_LH2[r];
                float di   = node_dinv(node);
                float4 ac   = ((const float4*)g_acc1)[(size_t)r * 32 + c4];
                float4 self = ((const float4*)(g_h1s + (size_t)g_slotH1[node] * HDIM))[c4];
                float4 b4   = ((const float4*)bias)[c4];
                v.x = fmaxf(fmaf(fmaf(self.x, di, ac.x), di, b4.x), 0.f);
                v.y = fmaxf(fmaf(fmaf(self.y, di, ac.y), di, b4.y), 0.f);
                v.z = fmaxf(fmaf(fmaf(self.z, di, ac.z), di, b4.z), 0.f);
                v.w = fmaxf(fmaf(fmaf(self.w, di, ac.w), di, b4.w), 0.f);
            }
        }
        __nv_bfloat162 h01 = __floats2bfloat162_rn(v.x, v.y);
        __nv_bfloat162 h23 = __floats2bfloat162_rn(v.z, v.w);
        float2 f01 = __bfloat1622float2(h01);
        float2 f23 = __bfloat1622float2(h23);
        __nv_bfloat162 l01 = __floats2bfloat162_rn(v.x - f01.x, v.y - f01.y);
        __nv_bfloat162 l23 = __floats2bfloat162_rn(v.z - f23.x, v.w - f23.y);
        uint32_t addr = tile_addr(row, c4 * 4);
        uint2 uh, ul;
        uh.x = *(uint32_t*)&h01; uh.y = *(uint32_t*)&h23;
        ul.x = *(uint32_t*)&l01; ul.y = *(uint32_t*)&l23;
        *(uint2*)(smem + SM_AHI + addr) = uh;
        *(uint2*)(smem + SM_ALO + addr) = ul;
    }
    __syncthreads();

    float acc[16][4];
#pragma unroll
    for (int i = 0; i < 16; i++)
#pragma unroll
        for (int j = 0; j < 4; j++) acc[i][j] = 0.f;

    const int mb0 = wid * 2;
    const int ablk = lane >> 3;
    const int arow = lane & 7;
    const int a_mblk  = mb0 + (ablk & 1);
    const int a_khalf = ablk >> 1;
    const int b_noff  = ablk >> 1;
    const int b_khalf = ablk & 1;

#pragma unroll
    for (int k16 = 0; k16 < 8; k16++) {
        uint32_t a_addr = sbase + (uint32_t)((((a_mblk * 8 + k16) * 2 + a_khalf) * 128) + arow * 16);
        uint32_t ahi[4], alo[4];
        ldsm4(ahi, a_addr + SM_AHI);
        ldsm4(alo, a_addr + SM_ALO);
#pragma unroll
        for (int nb2 = 0; nb2 < 8; nb2++) {
            int nblk = nb2 * 2 + b_noff;
            uint32_t b_addr = sbase + (uint32_t)((((nblk * 8 + k16) * 2 + b_khalf) * 128) + arow * 16);
            uint32_t bh[4], bl[4];
            ldsm4(bh, b_addr + SM_BHI);
            ldsm4(bl, b_addr + SM_BLO);
            mma_bf16(acc[nb2 * 2],     ahi, bh[0], bh[1]);
            mma_bf16(acc[nb2 * 2],     ahi, bl[0], bl[1]);
            mma_bf16(acc[nb2 * 2],     alo, bh[0], bh[1]);
            mma_bf16(acc[nb2 * 2 + 1], ahi, bh[2], bh[3]);
            mma_bf16(acc[nb2 * 2 + 1], ahi, bl[2], bl[3]);
            mma_bf16(acc[nb2 * 2 + 1], alo, bh[2], bh[3]);
        }
    }

    int g = lane >> 2;
    int q = lane & 3;
    int r0 = rowBase + wid * 16 + g;
    int r1 = r0 + 8;
#pragma unroll
    for (int nb = 0; nb < 16; nb++) {
        int col = nb * 8 + q * 2;
        if (r0 < cnt) *(float2*)(O + (size_t)r0 * HDIM + col) = make_float2(acc[nb][0], acc[nb][1]);
        if (r1 < cnt) *(float2*)(O + (size_t)r1 * HDIM + col) = make_float2(acc[nb][2], acc[nb][3]);
    }
}

// ---------------- agg1: acc1[slot] += dinv[src] * h1s[slotH1[src]] ---------------
__global__ __launch_bounds__(256) void k_agg1() {
    int gw   = (blockIdx.x * blockDim.x + threadIdx.x) >> 5;
    int lane = threadIdx.x & 31;
    int nw   = (gridDim.x * blockDim.x) >> 5;
    int cnt  = g_cntEB1; if (cnt > CAP_EB1) cnt = CAP_EB1;
    for (int i = gw; i < cnt; i += nw) {
        int2 e  = g_EB1[i];
        float w = node_dinv(e.y);
        int   r = g_slotH1[e.y];
        float4 v = ((const float4*)(g_h1s + (size_t)r * HDIM))[lane];
        float* dst = g_acc1 + (size_t)e.x * HDIM + lane * 4;
        atomicAdd(dst + 0, v.x * w);
        atomicAdd(dst + 1, v.y * w);
        atomicAdd(dst + 2, v.z * w);
        atomicAdd(dst + 3, v.w * w);
    }
}

// ---------------- final: agg2 (V2 only) + readout --------------------------------
__global__ __launch_bounds__(512) void k_final(const float* __restrict__ b2,
                                               const float* __restrict__ fcw,
                                               const float* __restrict__ fcb,
                                               float* __restrict__ out) {
    __shared__ float sa[CAP_V2 * HDIM];   // 32KB
    __shared__ float sred[128];
    int tid = threadIdx.x;
    int t   = tid & 127;       // dim
    int grp = tid >> 7;        // 0..3

    for (int i = tid; i < CAP_V2 * HDIM; i += 512) sa[i] = 0.f;
    __syncthreads();

    int cnt2 = g_cntEB2; if (cnt2 > CAP_EB2) cnt2 = CAP_EB2;
    for (int j = grp; j < cnt2; j += 4) {
        int2 e = g_EB2[j];
        float w = node_dinv(e.y);
        atomicAdd(&sa[e.x * HDIM + t], w * g_h2s[(size_t)g_slotH2[e.y] * HDIM + t]);
    }
    __syncthreads();

    int cv2 = g_cntV2; if (cv2 > CAP_V2) cv2 = CAP_V2;
    for (int s = grp; s < cv2; s += 4) {
        int   v  = g_LV2[s];
        float di = node_dinv(v);
        float self = g_h2s[(size_t)g_slotH2[v] * HDIM + t];
        float a2 = fmaf(fmaf(self, di, sa[s * HDIM + t]), di, b2[t]);
        sa[s * HDIM + t] = fmaxf(a2, 0.f);
    }
    __syncthreads();

    if (tid < 128) {
        int cev = g_cntEV2;
        int lim = cev > CAP_EV2 ? CAP_EV2 : cev;
        float nsum = 0.f;
        for (int j = 0; j < lim; j++) {
            int s = g_EV2[j];
            nsum += sa[g_slotV2[s] * HDIM + t];
        }
        float cntf = fmaxf((float)cev, 1.f);
        sred[t] = sa[t] * fcw[t] + (nsum / cntf) * fcw[HDIM + t];
    }
    __syncthreads();
    if (tid == 0) {
        float v = fcb[0];
        for (int j = 0; j < 128; j++) v += sred[j];
        out[0] = v;
    }
}

// ---------------- launcher ---------------------------------------------------------
extern "C" void kernel_launch(void* const* d_in, const int* in_sizes, int n_in,
                              void* d_out, int out_size) {
    const float* x   = nullptr;
    const void*  ei  = nullptr;
    const float* w1  = nullptr;
    const float* b1  = nullptr;
    const float* w2  = nullptr;
    const float* b2  = nullptr;
    const float* fcw = nullptr;
    const float* fcb = nullptr;
    for (int i = 0; i < n_in; i++) {
        switch (in_sizes[i]) {
            case 12800000: x   = (const float*)d_in[i];     break;
            case 3200000:  ei  = d_in[i];                   break;
            case 100000:   break;
            case 16384:    if (!w1) w1 = (const float*)d_in[i];
                           else      w2 = (const float*)d_in[i]; break;
            case 128:      if (!b1) b1 = (const float*)d_in[i];
                           else      b2 = (const float*)d_in[i]; break;
            case 256:      fcw = (const float*)d_in[i];     break;
            case 1:        fcb = (const float*)d_in[i];     break;
            default: break;
        }
    }
    float* out = (float*)d_out;

    float *p_h1s = nullptr, *p_h2s = nullptr;
    int *p_LH1 = nullptr, *p_cntH1 = nullptr, *p_cntH2 = nullptr;
    __nv_bfloat16 *p_w1hi = nullptr, *p_w1lo = nullptr, *p_w2hi = nullptr, *p_w2lo = nullptr;
    cudaGetSymbolAddress((void**)&p_h1s,  g_h1s);
    cudaGetSymbolAddress((void**)&p_h2s,  g_h2s);
    cudaGetSymbolAddress((void**)&p_LH1,  g_LH1);
    cudaGetSymbolAddress((void**)&p_cntH1, g_cntH1);
    cudaGetSymbolAddress((void**)&p_cntH2, g_cntH2);
    cudaGetSymbolAddress((void**)&p_w1hi, g_w1hi);
    cudaGetSymbolAddress((void**)&p_w1lo, g_w1lo);
    cudaGetSymbolAddress((void**)&p_w2hi, g_w2hi);
    cudaGetSymbolAddress((void**)&p_w2lo, g_w2lo);

    cudaFuncSetAttribute(k_gemm_s<0>, cudaFuncAttributeMaxDynamicSharedMemorySize, SM_TOT);
    cudaFuncSetAttribute(k_gemm_s<1>, cudaFuncAttributeMaxDynamicSharedMemorySize, SM_TOT);

    k_init<<<GN + 512, 256>>>((const long long*)ei);        // + acc1 zeroing
    k_prep<<<GE4 + 128, 256>>>(ei, w1, w2);                 // + wconv
    k_f1  <<<GE4, 256>>>(ei);
    k_f2  <<<GE4, 256>>>(ei);

    // sparse layer 1 (doesn't need degrees)
    k_gemm_s<0><<<CAP_H1 / 128, 256, SM_TOT>>>(x, p_LH1, p_cntH1, CAP_H1, nullptr,
                                               p_w1hi, p_w1lo, p_h1s);
    // restricted degree histogram (needs final bmH1; overlaps nothing GEMM1 uses)
    k_hist<<<GE4, 256>>>(ei);
    k_agg1<<<256, 256>>>();

    // sparse layer 2: finalize a1 inline in A-load
    k_gemm_s<1><<<CAP_H2 / 128, 256, SM_TOT>>>(nullptr, nullptr, p_cntH2, CAP_H2, b1,
                                               p_w2hi, p_w2lo, p_h2s);

    // agg2 at V2 + readout
    k_final<<<1, 512>>>(b2, fcw, fcb, out);
}

// round 13
// speedup vs baseline: 1.0749x; 1.0749x over previous
#include <cuda_runtime.h>
#include <cuda_bf16.h>
#include <cstdint>

#define N_NODES 100000
#define E_EDGES 1600000
#define HDIM    128
#define BMW     ((N_NODES + 31) / 32)     // 3125 bitmap words
#define GE      ((E_EDGES + 255) / 256)   // 6250 edge blocks (1 edge/thread)
#define GN      ((N_NODES + 255) / 256)   // 391

#define CAP_V2   64
#define CAP_EV2  256
#define CAP_H2   4096
#define CAP_EB2  8192
#define CAP_H1   16384
#define CAP_EB1  131072

// ---------------- scratch (static device globals) ------------------------------
__device__ int      g_is64;
__device__ int      g_degi[N_NODES];
__device__ float    g_dinv[N_NODES];
__device__ uint32_t g_bmV2[BMW], g_bmH2[BMW], g_bmH1[BMW];
__device__ int      g_slotV2[N_NODES], g_slotH2[N_NODES], g_slotH1[N_NODES];
__device__ int      g_LV2[CAP_V2], g_LH2[CAP_H2], g_LH1[CAP_H1];
__device__ int      g_EV2[CAP_EV2];
__device__ int2     g_EB1[CAP_EB1], g_EB2[CAP_EB2];
__device__ int      g_cntV2, g_cntEV2, g_cntH2, g_cntH1, g_cntEB1, g_cntEB2;
__device__ __align__(16) float g_h1s [(size_t)CAP_H1 * HDIM];  // h1 compact
__device__ __align__(16) float g_acc1[(size_t)CAP_H2 * HDIM];  // agg1 accum
__device__ __align__(16) float g_h2s [(size_t)CAP_H2 * HDIM];  // h2 compact
// pre-tiled bf16 weight images (exact SMEM 8x8-block layout, 32KB each)
__device__ __align__(16) __nv_bfloat16 g_w1hi[16384];
__device__ __align__(16) __nv_bfloat16 g_w1lo[16384];
__device__ __align__(16) __nv_bfloat16 g_w2hi[16384];
__device__ __align__(16) __nv_bfloat16 g_w2lo[16384];

// ---------------- PTX helpers ----------------------------------------------------
__device__ __forceinline__ uint32_t smem_u32(const void* p) {
    uint32_t a;
    asm("{ .reg .u64 t; cvta.to.shared.u64 t, %1; cvt.u32.u64 %0, t; }" : "=r"(a) : "l"(p));
    return a;
}
__device__ __forceinline__ void ldsm4(uint32_t* r, uint32_t addr) {
    asm volatile("ldmatrix.sync.aligned.m8n8.x4.shared.b16 {%0,%1,%2,%3}, [%4];"
                 : "=r"(r[0]), "=r"(r[1]), "=r"(r[2]), "=r"(r[3]) : "r"(addr));
}
__device__ __forceinline__ void mma_bf16(float* c, const uint32_t* a, uint32_t b0, uint32_t b1) {
    asm volatile("mma.sync.aligned.m16n8k16.row.col.f32.bf16.bf16.f32 "
                 "{%0,%1,%2,%3}, {%4,%5,%6,%7}, {%8,%9}, {%0,%1,%2,%3};"
                 : "+f"(c[0]), "+f"(c[1]), "+f"(c[2]), "+f"(c[3])
                 : "r"(a[0]), "r"(a[1]), "r"(a[2]), "r"(a[3]), "r"(b0), "r"(b1));
}
__device__ __forceinline__ uint32_t tile_addr(int r, int k) {
    uint32_t blk = (uint32_t)(((r >> 3) * 8 + (k >> 4)) * 2 + ((k >> 3) & 1));
    return blk * 128 + (uint32_t)((r & 7) * 16 + (k & 7) * 2);
}
__device__ __forceinline__ void edge_decode(const void* eiv, int e, int& s, int& d) {
    if (g_is64) {
        const long long* p = (const long long*)eiv;
        s = (int)p[e];
        d = (int)p[E_EDGES + e];
    } else {
        const int* p = (const int*)eiv;
        s = p[e];
        d = p[E_EDGES + e];
    }
    if ((unsigned)s >= N_NODES) s = 0;
    if ((unsigned)d >= N_NODES) d = 0;
}
__device__ __forceinline__ void try_append(uint32_t* bm, int* slotArr, int* list,
                                           int* cnt, int cap, int node) {
    uint32_t mask = 1u << (node & 31);
    uint32_t old = atomicOr(&bm[node >> 5], mask);
    if (!(old & mask)) {
        int s = atomicAdd(cnt, 1);
        if (s < cap) { slotArr[node] = s; list[s] = node; }
    }
}

// ---------------- init: zero degi/bitmaps/acc1 + seed node 0 ---------------------
__global__ __launch_bounds__(1024) void k_init(const long long* __restrict__ ei) {
    int i = blockIdx.x * blockDim.x + threadIdx.x;   // 512 x 1024
    if (i < N_NODES) g_degi[i] = 0;
    if (i >= 1 && i < BMW) { g_bmV2[i] = 0; g_bmH2[i] = 0; g_bmH1[i] = 0; }
    if (i < CAP_H2 * HDIM) g_acc1[i] = 0.f;
    if (i == 0) {
        g_bmV2[0] = 1u; g_bmH2[0] = 1u; g_bmH1[0] = 1u;          // node 0 seeded
        g_slotV2[0] = 0; g_slotH2[0] = 0; g_slotH1[0] = 0;
        g_LV2[0] = 0;    g_LH2[0] = 0;   g_LH1[0] = 0;
        g_cntV2 = 1; g_cntH2 = 1; g_cntH1 = 1;
        g_cntEV2 = 0; g_cntEB1 = 0; g_cntEB2 = 0;
        int is64 = 1;
#pragma unroll
        for (int j = 0; j < 16; j++) {
            long long v = ei[j];
            if (v < 0 || v >= N_NODES) { is64 = 0; break; }
        }
        g_is64 = is64;
    }
}

// ---------------- pass 0: histogram + V2 frontier (+ wconv extras) ---------------
__global__ __launch_bounds__(256) void k_prep(const void* __restrict__ eiv,
                                              const float* __restrict__ w1,
                                              const float* __restrict__ w2) {
    if ((int)blockIdx.x >= GE) {
        int i = ((int)blockIdx.x - GE) * 256 + threadIdx.x;      // 0..32767
        if (i < 32768) {
            const float* w = (i < 16384) ? w1 : w2;
            __nv_bfloat16* hi = (i < 16384) ? g_w1hi : g_w2hi;
            __nv_bfloat16* lo = (i < 16384) ? g_w1lo : g_w2lo;
            int j = i & 16383;
            int k = j >> 7, n = j & 127;                          // B[n][k] = w[k][n]
            float v = w[j];
            __nv_bfloat16 h = __float2bfloat16(v);
            __nv_bfloat16 l = __float2bfloat16(v - __bfloat162float(h));
            uint32_t a = tile_addr(n, k);
            *(__nv_bfloat16*)((char*)hi + a) = h;
            *(__nv_bfloat16*)((char*)lo + a) = l;
        }
        return;
    }
    int e = blockIdx.x * 256 + threadIdx.x;
    if (e >= E_EDGES) return;
    int s, d;
    edge_decode(eiv, e, s, d);
    atomicAdd(&g_degi[d], 1);
    if (d == 0) {
        int ev = atomicAdd(&g_cntEV2, 1);
        if (ev < CAP_EV2) g_EV2[ev] = s;
        try_append(g_bmV2, g_slotV2, g_LV2, &g_cntV2, CAP_V2, s);
        try_append(g_bmH2, g_slotH2, g_LH2, &g_cntH2, CAP_H2, s);
        try_append(g_bmH1, g_slotH1, g_LH1, &g_cntH1, CAP_H1, s);
    }
}

// ---------------- pass 1: edges into V2 -> EB2, discover H2 (+ dinv extras) ------
__global__ __launch_bounds__(256) void k_f1(const void* __restrict__ eiv) {
    if ((int)blockIdx.x >= GE) {
        int i = ((int)blockIdx.x - GE) * 256 + threadIdx.x;
        if (i < N_NODES) g_dinv[i] = rsqrtf((float)g_degi[i] + 1.f);
        return;
    }
    int e = blockIdx.x * 256 + threadIdx.x;
    if (e >= E_EDGES) return;
    int s, d;
    edge_decode(eiv, e, s, d);
    if (g_bmV2[d >> 5] & (1u << (d & 31))) {
        int i = atomicAdd(&g_cntEB2, 1);
        if (i < CAP_EB2) g_EB2[i] = make_int2(g_slotV2[d], s);
        try_append(g_bmH2, g_slotH2, g_LH2, &g_cntH2, CAP_H2, s);
        try_append(g_bmH1, g_slotH1, g_LH1, &g_cntH1, CAP_H1, s);
    }
}

// ---------------- pass 2: edges into H2 -> EB1, discover H1 ----------------------
__global__ __launch_bounds__(256) void k_f2(const void* __restrict__ eiv) {
    int e = blockIdx.x * 256 + threadIdx.x;
    if (e >= E_EDGES) return;
    int s, d;
    edge_decode(eiv, e, s, d);
    if (g_bmH2[d >> 5] & (1u << (d & 31))) {
        int i = atomicAdd(&g_cntEB1, 1);
        if (i < CAP_EB1) g_EB1[i] = make_int2(g_slotH2[d], s);
        try_append(g_bmH1, g_slotH1, g_LH1, &g_cntH1, CAP_H1, s);
    }
}

// ---------------- sparse HMMA GEMM --------------------------------------------
// MODE 0: rows gathered from A via idx (layer 1, A = x)
// MODE 1: rows = relu((acc1[r] + h1s[slotH1[LH2[r]]]*di)*di + bias)  (layer 2)
#define SM_AHI  0
#define SM_ALO  32768
#define SM_BHI  65536
#define SM_BLO  98304
#define SM_TOT  131072

template <int MODE>
__global__ __launch_bounds__(256)
void k_gemm_s(const float* __restrict__ A,
              const int* __restrict__ idx,
              const int* __restrict__ cntp, int cap,
              const float* __restrict__ bias,
              const __nv_bfloat16* __restrict__ Whi,
              const __nv_bfloat16* __restrict__ Wlo,
              float* __restrict__ O) {
    int cnt = *cntp; if (cnt > cap) cnt = cap;
    const int rowBase = blockIdx.x * 128;
    if (rowBase >= cnt) return;

    extern __shared__ char smem[];
    const uint32_t sbase = smem_u32(smem);
    const int tid  = threadIdx.x;
    const int wid  = tid >> 5;
    const int lane = tid & 31;

#pragma unroll
    for (int i = 0; i < 8; i++) {
        int k = i * 256 + tid;
        ((uint4*)(smem + SM_BHI))[k] = ((const uint4*)Whi)[k];
        ((uint4*)(smem + SM_BLO))[k] = ((const uint4*)Wlo)[k];
    }

#pragma unroll
    for (int i = 0; i < 16; i++) {
        int f4  = i * 256 + tid;
        int row = f4 >> 5;
        int c4  = f4 & 31;
        int r   = rowBase + row;
        float4 v = make_float4(0.f, 0.f, 0.f, 0.f);
        if (r < cnt) {
            if (MODE == 0) {
                int node = idx[r];
                v = *(const float4*)(A + (size_t)node * HDIM + c4 * 4);
            } else {
                int   node = g_LH2[r];
                float di   = g_dinv[node];
                float4 ac   = ((const float4*)g_acc1)[(size_t)r * 32 + c4];
                float4 self = ((const float4*)(g_h1s + (size_t)g_slotH1[node] * HDIM))[c4];
                float4 b4   = ((const float4*)bias)[c4];
                v.x = fmaxf(fmaf(fmaf(self.x, di, ac.x), di, b4.x), 0.f);
                v.y = fmaxf(fmaf(fmaf(self.y, di, ac.y), di, b4.y), 0.f);
                v.z = fmaxf(fmaf(fmaf(self.z, di, ac.z), di, b4.z), 0.f);
                v.w = fmaxf(fmaf(fmaf(self.w, di, ac.w), di, b4.w), 0.f);
            }
        }
        __nv_bfloat162 h01 = __floats2bfloat162_rn(v.x, v.y);
        __nv_bfloat162 h23 = __floats2bfloat162_rn(v.z, v.w);
        float2 f01 = __bfloat1622float2(h01);
        float2 f23 = __bfloat1622float2(h23);
        __nv_bfloat162 l01 = __floats2bfloat162_rn(v.x - f01.x, v.y - f01.y);
        __nv_bfloat162 l23 = __floats2bfloat162_rn(v.z - f23.x, v.w - f23.y);
        uint32_t addr = tile_addr(row, c4 * 4);
        uint2 uh, ul;
        uh.x = *(uint32_t*)&h01; uh.y = *(uint32_t*)&h23;
        ul.x = *(uint32_t*)&l01; ul.y = *(uint32_t*)&l23;
        *(uint2*)(smem + SM_AHI + addr) = uh;
        *(uint2*)(smem + SM_ALO + addr) = ul;
    }
    __syncthreads();

    float acc[16][4];
#pragma unroll
    for (int i = 0; i < 16; i++)
#pragma unroll
        for (int j = 0; j < 4; j++) acc[i][j] = 0.f;

    const int mb0 = wid * 2;
    const int ablk = lane >> 3;
    const int arow = lane & 7;
    const int a_mblk  = mb0 + (ablk & 1);
    const int a_khalf = ablk >> 1;
    const int b_noff  = ablk >> 1;
    const int b_khalf = ablk & 1;

#pragma unroll
    for (int k16 = 0; k16 < 8; k16++) {
        uint32_t a_addr = sbase + (uint32_t)((((a_mblk * 8 + k16) * 2 + a_khalf) * 128) + arow * 16);
        uint32_t ahi[4], alo[4];
        ldsm4(ahi, a_addr + SM_AHI);
        ldsm4(alo, a_addr + SM_ALO);
#pragma unroll
        for (int nb2 = 0; nb2 < 8; nb2++) {
            int nblk = nb2 * 2 + b_noff;
            uint32_t b_addr = sbase + (uint32_t)((((nblk * 8 + k16) * 2 + b_khalf) * 128) + arow * 16);
            uint32_t bh[4], bl[4];
            ldsm4(bh, b_addr + SM_BHI);
            ldsm4(bl, b_addr + SM_BLO);
            mma_bf16(acc[nb2 * 2],     ahi, bh[0], bh[1]);
            mma_bf16(acc[nb2 * 2],     ahi, bl[0], bl[1]);
            mma_bf16(acc[nb2 * 2],     alo, bh[0], bh[1]);
            mma_bf16(acc[nb2 * 2 + 1], ahi, bh[2], bh[3]);
            mma_bf16(acc[nb2 * 2 + 1], ahi, bl[2], bl[3]);
            mma_bf16(acc[nb2 * 2 + 1], alo, bh[2], bh[3]);
        }
    }

    int g = lane >> 2;
    int q = lane & 3;
    int r0 = rowBase + wid * 16 + g;
    int r1 = r0 + 8;
#pragma unroll
    for (int nb = 0; nb < 16; nb++) {
        int col = nb * 8 + q * 2;
        if (r0 < cnt) *(float2*)(O + (size_t)r0 * HDIM + col) = make_float2(acc[nb][0], acc[nb][1]);
        if (r1 < cnt) *(float2*)(O + (size_t)r1 * HDIM + col) = make_float2(acc[nb][2], acc[nb][3]);
    }
}

// ---------------- agg1: acc1[slot] += dinv[src] * h1s[slotH1[src]] ---------------
__global__ __launch_bounds__(256) void k_agg1() {
    int gw   = (blockIdx.x * blockDim.x + threadIdx.x) >> 5;
    int lane = threadIdx.x & 31;
    int nw   = (gridDim.x * blockDim.x) >> 5;
    int cnt  = g_cntEB1; if (cnt > CAP_EB1) cnt = CAP_EB1;
    for (int i = gw; i < cnt; i += nw) {
        int2 e  = g_EB1[i];
        float w = g_dinv[e.y];
        int   r = g_slotH1[e.y];
        float4 v = ((const float4*)(g_h1s + (size_t)r * HDIM))[lane];
        float* dst = g_acc1 + (size_t)e.x * HDIM + lane * 4;
        atomicAdd(dst + 0, v.x * w);
        atomicAdd(dst + 1, v.y * w);
        atomicAdd(dst + 2, v.z * w);
        atomicAdd(dst + 3, v.w * w);
    }
}

// ---------------- final: agg2 (V2 only) + readout --------------------------------
__global__ __launch_bounds__(512) void k_final(const float* __restrict__ b2,
                                               const float* __restrict__ fcw,
                                               const float* __restrict__ fcb,
                                               float* __restrict__ out) {
    __shared__ float sa[CAP_V2 * HDIM];   // 32KB
    __shared__ float sred[128];
    int tid = threadIdx.x;
    int t   = tid & 127;       // dim
    int grp = tid >> 7;        // 0..3

    for (int i = tid; i < CAP_V2 * HDIM; i += 512) sa[i] = 0.f;
    __syncthreads();

    int cnt2 = g_cntEB2; if (cnt2 > CAP_EB2) cnt2 = CAP_EB2;
    for (int j = grp; j < cnt2; j += 4) {
        int2 e = g_EB2[j];
        float w = g_dinv[e.y];
        atomicAdd(&sa[e.x * HDIM + t], w * g_h2s[(size_t)g_slotH2[e.y] * HDIM + t]);
    }
    __syncthreads();

    int cv2 = g_cntV2; if (cv2 > CAP_V2) cv2 = CAP_V2;
    for (int s = grp; s < cv2; s += 4) {
        int   v  = g_LV2[s];
        float di = g_dinv[v];
        float self = g_h2s[(size_t)g_slotH2[v] * HDIM + t];
        float a2 = fmaf(fmaf(self, di, sa[s * HDIM + t]), di, b2[t]);
        sa[s * HDIM + t] = fmaxf(a2, 0.f);
    }
    __syncthreads();

    if (tid < 128) {
        int cev = g_cntEV2;
        int lim = cev > CAP_EV2 ? CAP_EV2 : cev;
        float nsum = 0.f;
        for (int j = 0; j < lim; j++) {
            int s = g_EV2[j];
            nsum += sa[g_slotV2[s] * HDIM + t];
        }
        float cntf = fmaxf((float)cev, 1.f);
        sred[t] = sa[t] * fcw[t] + (nsum / cntf) * fcw[HDIM + t];
    }
    __syncthreads();
    if (tid == 0) {
        float v = fcb[0];
        for (int j = 0; j < 128; j++) v += sred[j];
        out[0] = v;
    }
}

// ---------------- launcher ---------------------------------------------------------
extern "C" void kernel_launch(void* const* d_in, const int* in_sizes, int n_in,
                              void* d_out, int out_size) {
    const float* x   = nullptr;
    const void*  ei  = nullptr;
    const float* w1  = nullptr;
    const float* b1  = nullptr;
    const float* w2  = nullptr;
    const float* b2  = nullptr;
    const float* fcw = nullptr;
    const float* fcb = nullptr;
    for (int i = 0; i < n_in; i++) {
        switch (in_sizes[i]) {
            case 12800000: x   = (const float*)d_in[i];     break;
            case 3200000:  ei  = d_in[i];                   break;
            case 100000:   break;
            case 16384:    if (!w1) w1 = (const float*)d_in[i];
                           else      w2 = (const float*)d_in[i]; break;
            case 128:      if (!b1) b1 = (const float*)d_in[i];
                           else      b2 = (const float*)d_in[i]; break;
            case 256:      fcw = (const float*)d_in[i];     break;
            case 1:        fcb = (const float*)d_in[i];     break;
            default: break;
        }
    }
    float* out = (float*)d_out;

    float *p_h1s = nullptr, *p_h2s = nullptr;
    int *p_LH1 = nullptr, *p_cntH1 = nullptr, *p_cntH2 = nullptr;
    __nv_bfloat16 *p_w1hi = nullptr, *p_w1lo = nullptr, *p_w2hi = nullptr, *p_w2lo = nullptr;
    cudaGetSymbolAddress((void**)&p_h1s,  g_h1s);
    cudaGetSymbolAddress((void**)&p_h2s,  g_h2s);
    cudaGetSymbolAddress((void**)&p_LH1,  g_LH1);
    cudaGetSymbolAddress((void**)&p_cntH1, g_cntH1);
    cudaGetSymbolAddress((void**)&p_cntH2, g_cntH2);
    cudaGetSymbolAddress((void**)&p_w1hi, g_w1hi);
    cudaGetSymbolAddress((void**)&p_w1lo, g_w1lo);
    cudaGetSymbolAddress((void**)&p_w2hi, g_w2hi);
    cudaGetSymbolAddress((void**)&p_w2lo, g_w2lo);

    cudaFuncSetAttribute(k_gemm_s<0>, cudaFuncAttributeMaxDynamicSharedMemorySize, SM_TOT);
    cudaFuncSetAttribute(k_gemm_s<1>, cudaFuncAttributeMaxDynamicSharedMemorySize, SM_TOT);

    k_init<<<512, 1024>>>((const long long*)ei);
    k_prep<<<GE + 128, 256>>>(ei, w1, w2);                  // + wconv extras
    k_f1  <<<GE + GN, 256>>>(ei);                           // + dinv extras
    k_f2  <<<GE, 256>>>(ei);

    // sparse layer 1: h1 at H1 nodes (gathered rows of x)
    k_gemm_s<0><<<CAP_H1 / 128, 256, SM_TOT>>>(x, p_LH1, p_cntH1, CAP_H1, nullptr,
                                               p_w1hi, p_w1lo, p_h1s);
    k_agg1<<<256, 256>>>();

    // sparse layer 2: finalize a1 inline in A-load
    k_gemm_s<1><<<CAP_H2 / 128, 256, SM_TOT>>>(nullptr, nullptr, p_cntH2, CAP_H2, b1,
                                               p_w2hi, p_w2lo, p_h2s);

    // agg2 at V2 + readout
    k_final<<<1, 512>>>(b2, fcw, fcb, out);
}